// round 4
// baseline (speedup 1.0000x reference)
#include <cuda_runtime.h>

// Problem shape (fixed by dataset)
#define BB 8
#define DD 8
#define HH 512
#define WW 1024
#define KK 5
#define PP (HH * WW)       // 524288 pixels per image
#define PV (PP / 4)        // float4 / int4 granularity

#define DELTA_V 0.5f
#define DELTA_D 3.0f
#define GAMMA_W 0.001f

// Scratch (no allocations allowed -> __device__ globals)
__device__ float g_sums[BB * KK * DD];
__device__ float g_counts[BB * KK];
__device__ float g_varsum[BB * KK];
__device__ float g_centers[BB * KK * DD];
__device__ float g_distb[BB];
__device__ float g_regb[BB];
__device__ float g_Nb[BB];

// ---------------------------------------------------------------------------
// Kernel 0: zero accumulators
// ---------------------------------------------------------------------------
__global__ void k_zero() {
    int i = threadIdx.x;
    if (i < BB * KK * DD) g_sums[i] = 0.f;
    if (i < BB * KK) { g_counts[i] = 0.f; g_varsum[i] = 0.f; }
}

__device__ __forceinline__ float warp_sum(float v) {
    #pragma unroll
    for (int o = 16; o > 0; o >>= 1) v += __shfl_down_sync(0xffffffffu, v, o);
    return v;
}

// ---------------------------------------------------------------------------
// Kernel 1: segment sums + counts  (one-hot FMA, all-static register indices)
// grid: (CHUNKS, B), block: 256
// ---------------------------------------------------------------------------
__global__ void __launch_bounds__(256) k_pass1(const float4* __restrict__ emb,
                                               const int4* __restrict__ mask) {
    const int b = blockIdx.y;
    const float4* __restrict__ eb = emb + (size_t)b * DD * PV;
    const int4* __restrict__ mb = mask + (size_t)b * PV;

    float s[KK * DD];
    float cnt[KK];
    #pragma unroll
    for (int i = 0; i < KK * DD; i++) s[i] = 0.f;
    #pragma unroll
    for (int k = 0; k < KK; k++) cnt[k] = 0.f;

    const int stride = gridDim.x * blockDim.x;
    for (int i = blockIdx.x * blockDim.x + threadIdx.x; i < PV; i += stride) {
        int4 mm = mb[i];
        float w0[KK], w1[KK], w2[KK], w3[KK];
        #pragma unroll
        for (int k = 0; k < KK; k++) {
            w0[k] = (mm.x == k + 1) ? 1.f : 0.f;
            w1[k] = (mm.y == k + 1) ? 1.f : 0.f;
            w2[k] = (mm.z == k + 1) ? 1.f : 0.f;
            w3[k] = (mm.w == k + 1) ? 1.f : 0.f;
            cnt[k] += (w0[k] + w1[k]) + (w2[k] + w3[k]);
        }
        #pragma unroll
        for (int d = 0; d < DD; d++) {
            float4 ev = eb[(size_t)d * PV + i];
            #pragma unroll
            for (int k = 0; k < KK; k++) {
                float a = s[k * DD + d];
                a = fmaf(ev.x, w0[k], a);
                a = fmaf(ev.y, w1[k], a);
                a = fmaf(ev.z, w2[k], a);
                a = fmaf(ev.w, w3[k], a);
                s[k * DD + d] = a;
            }
        }
    }

    // Block reduction: 8 warps x 45 values
    __shared__ float red[8][48];
    const int warp = threadIdx.x >> 5, lane = threadIdx.x & 31;
    #pragma unroll
    for (int v = 0; v < KK * DD; v++) {
        float r = warp_sum(s[v]);
        if (lane == 0) red[warp][v] = r;
    }
    #pragma unroll
    for (int k = 0; k < KK; k++) {
        float r = warp_sum(cnt[k]);
        if (lane == 0) red[warp][KK * DD + k] = r;
    }
    __syncthreads();
    const int t = threadIdx.x;
    if (t < KK * DD + KK) {
        float acc = 0.f;
        #pragma unroll
        for (int w = 0; w < 8; w++) acc += red[w][t];
        if (t < KK * DD) atomicAdd(&g_sums[b * KK * DD + t], acc);
        else             atomicAdd(&g_counts[b * KK + (t - KK * DD)], acc);
    }
}

// ---------------------------------------------------------------------------
// Kernel 2: centers + pairwise distance loss + regularizer (tiny)
// one thread per batch image
// ---------------------------------------------------------------------------
__global__ void k_mid() {
    const int b = threadIdx.x;
    if (b >= BB) return;

    float cnt[KK], pres[KK];
    float N = 0.f;
    #pragma unroll
    for (int k = 0; k < KK; k++) {
        cnt[k] = g_counts[b * KK + k];
        pres[k] = (cnt[k] > 0.f) ? 1.f : 0.f;
        N += pres[k];
    }

    float c[KK][DD];
    #pragma unroll
    for (int k = 0; k < KK; k++) {
        float inv = 1.f / fmaxf(cnt[k], 1.f);
        #pragma unroll
        for (int d = 0; d < DD; d++) {
            float v = g_sums[b * KK * DD + k * DD + d] * inv;
            c[k][d] = v;
            g_centers[b * KK * DD + k * DD + d] = v;
        }
    }

    // pairwise hinge (i < j)
    float dist = 0.f;
    #pragma unroll
    for (int i = 0; i < KK; i++) {
        #pragma unroll
        for (int j = i + 1; j < KK; j++) {
            if (pres[i] > 0.f && pres[j] > 0.f) {
                float dsq = 0.f;
                #pragma unroll
                for (int d = 0; d < DD; d++) {
                    float df = c[i][d] - c[j][d];
                    dsq = fmaf(df, df, dsq);
                }
                float sd = sqrtf(dsq);
                float term = fmaxf(2.f * DELTA_D - sd, 0.f);
                dist += term * term;
            }
        }
    }
    float npairs = N * (N - 1.f) * 0.5f;
    g_distb[b] = dist / ((N > 1.f) ? npairs : 1.f);

    float reg = 0.f;
    #pragma unroll
    for (int k = 0; k < KK; k++) {
        if (pres[k] > 0.f) {
            float nsq = 0.f;
            #pragma unroll
            for (int d = 0; d < DD; d++) nsq = fmaf(c[k][d], c[k][d], nsq);
            reg += sqrtf(nsq);
        }
    }
    g_regb[b] = reg / fmaxf(N, 1.f);
    g_Nb[b] = N;
}

// ---------------------------------------------------------------------------
// Kernel 3: per-pixel variance term (centers gathered from shared)
// grid: (CHUNKS, B), block: 256
// ---------------------------------------------------------------------------
__global__ void __launch_bounds__(256) k_pass2(const float4* __restrict__ emb,
                                               const int4* __restrict__ mask) {
    __shared__ float cs[KK * DD];
    const int b = blockIdx.y;
    if (threadIdx.x < KK * DD) cs[threadIdx.x] = g_centers[b * KK * DD + threadIdx.x];
    __syncthreads();

    const float4* __restrict__ eb = emb + (size_t)b * DD * PV;
    const int4* __restrict__ mb = mask + (size_t)b * PV;

    float vs[KK];
    #pragma unroll
    for (int k = 0; k < KK; k++) vs[k] = 0.f;

    const int stride = gridDim.x * blockDim.x;
    for (int i = blockIdx.x * blockDim.x + threadIdx.x; i < PV; i += stride) {
        int4 mm = mb[i];
        int i0 = min(max(mm.x - 1, 0), KK - 1) * DD;
        int i1 = min(max(mm.y - 1, 0), KK - 1) * DD;
        int i2 = min(max(mm.z - 1, 0), KK - 1) * DD;
        int i3 = min(max(mm.w - 1, 0), KK - 1) * DD;

        float d0 = 0.f, d1 = 0.f, d2 = 0.f, d3 = 0.f;
        #pragma unroll
        for (int d = 0; d < DD; d++) {
            float4 ev = eb[(size_t)d * PV + i];
            float t0 = ev.x - cs[i0 + d]; d0 = fmaf(t0, t0, d0);
            float t1 = ev.y - cs[i1 + d]; d1 = fmaf(t1, t1, d1);
            float t2 = ev.z - cs[i2 + d]; d2 = fmaf(t2, t2, d2);
            float t3 = ev.w - cs[i3 + d]; d3 = fmaf(t3, t3, d3);
        }

        float v0 = fmaxf(sqrtf(d0) - DELTA_V, 0.f); v0 *= v0;
        float v1 = fmaxf(sqrtf(d1) - DELTA_V, 0.f); v1 *= v1;
        float v2 = fmaxf(sqrtf(d2) - DELTA_V, 0.f); v2 *= v2;
        float v3 = fmaxf(sqrtf(d3) - DELTA_V, 0.f); v3 *= v3;

        #pragma unroll
        for (int k = 0; k < KK; k++) {
            float a = vs[k];
            a += (mm.x == k + 1) ? v0 : 0.f;
            a += (mm.y == k + 1) ? v1 : 0.f;
            a += (mm.z == k + 1) ? v2 : 0.f;
            a += (mm.w == k + 1) ? v3 : 0.f;
            vs[k] = a;
        }
    }

    __shared__ float red[8][KK];
    const int warp = threadIdx.x >> 5, lane = threadIdx.x & 31;
    #pragma unroll
    for (int k = 0; k < KK; k++) {
        float r = warp_sum(vs[k]);
        if (lane == 0) red[warp][k] = r;
    }
    __syncthreads();
    if (threadIdx.x < KK) {
        float acc = 0.f;
        #pragma unroll
        for (int w = 0; w < 8; w++) acc += red[w][threadIdx.x];
        atomicAdd(&g_varsum[b * KK + threadIdx.x], acc);
    }
}

// ---------------------------------------------------------------------------
// Kernel 4: finalize -> out[0..3] = total, var, dist, reg
// ---------------------------------------------------------------------------
__global__ void k_final(float* __restrict__ out, int out_size) {
    if (threadIdx.x != 0 || blockIdx.x != 0) return;
    float sv = 0.f, sd = 0.f, sr = 0.f, hs = 0.f;
    #pragma unroll
    for (int b = 0; b < BB; b++) {
        float N = g_Nb[b];
        float lv = 0.f;
        #pragma unroll
        for (int k = 0; k < KK; k++) {
            float c = g_counts[b * KK + k];
            if (c > 0.f) lv += g_varsum[b * KK + k] / c;
        }
        lv /= fmaxf(N, 1.f);
        float has = (N > 0.f) ? 1.f : 0.f;
        sv += lv * has;
        sd += g_distb[b] * has;
        sr += g_regb[b] * has;
        hs += has;
    }
    float den = fmaxf(hs, 1.f);
    sv /= den; sd /= den; sr /= den;
    float total = sv + sd + GAMMA_W * sr;
    float res[4] = {total, sv, sd, sr};
    for (int i = 0; i < 4 && i < out_size; i++) out[i] = res[i];
}

// ---------------------------------------------------------------------------
extern "C" void kernel_launch(void* const* d_in, const int* in_sizes, int n_in,
                              void* d_out, int out_size) {
    const float4* emb = (const float4*)d_in[0];
    const int4* mask = (const int4*)d_in[1];

    k_zero<<<1, 512>>>();
    dim3 grid(64, BB);
    k_pass1<<<grid, 256>>>(emb, mask);
    k_mid<<<1, 32>>>();
    k_pass2<<<grid, 256>>>(emb, mask);
    k_final<<<1, 32>>>((float*)d_out, out_size);
}